// round 1
// baseline (speedup 1.0000x reference)
#include <cuda_runtime.h>
#include <cstdint>

#define NN   100000      // NC == NR
#define EN   2000000     // edges per direction
#define LN   500000      // label edges
#define Hd   64

// ---------------- scratch (device globals; no allocation) ----------------
__device__ float g_deg_c[NN];
__device__ float g_deg_r[NN];
__device__ float g_y  [NN * Hd];   // transformed src feats (reused 4x)
__device__ float g_acc[NN * Hd];   // scatter accumulator (reused 4x)
__device__ float g_hr [NN * Hd];
__device__ float g_hc [NN * Hd];
__device__ float g_zr [NN * Hd];
__device__ float g_zc [NN * Hd];
__device__ float g_Wt [Hd * 128];  // W_dec1 transposed: [j][k]

// ---------------- helpers ----------------
__device__ __forceinline__ void red_add4(float* a, float4 v) {
    asm volatile("red.global.add.v4.f32 [%0], {%1, %2, %3, %4};"
                 :: "l"(a), "f"(v.x), "f"(v.y), "f"(v.z), "f"(v.w)
                 : "memory");
}

// ---------------- degree count ----------------
__global__ void degree_k(const int* __restrict__ dst, float* __restrict__ deg) {
    int t = blockIdx.x * 256 + threadIdx.x;
    if (t < EN) atomicAdd(deg + __ldg(dst + t), 1.0f);
}

// ---------------- scatter-add: acc[dst] += y[src] (64 floats) ----------------
// one thread per (edge, float4-chunk): 16 chunks/edge
__global__ void scatter_add_k(const float4* __restrict__ y,
                              const int* __restrict__ src,
                              const int* __restrict__ dst,
                              float* __restrict__ acc) {
    int t = blockIdx.x * 256 + threadIdx.x;
    if (t >= EN * 16) return;
    int e = t >> 4;
    int c = t & 15;
    int s = __ldg(src + e);
    int d = __ldg(dst + e);
    float4 v = __ldg(y + s * 16 + c);
    red_add4(acc + (size_t)d * Hd + c * 4, v);
}

// ---------------- Y[N,64] = X[N,F] @ W[F,64] ----------------
// blockDim (64,4); 32 rows per block; 8 rows per thread
template <int F>
__global__ void __launch_bounds__(256)
node_gemm(const float* __restrict__ X, const float* __restrict__ W,
          float* __restrict__ Y, int N) {
    __shared__ float sW[F * Hd];
    int tid = threadIdx.y * 64 + threadIdx.x;
    for (int i = tid; i < F * Hd; i += 256) sW[i] = W[i];
    __syncthreads();

    int col  = threadIdx.x;
    int row0 = blockIdx.x * 32 + threadIdx.y;
    if (row0 >= N) return;

    float acc[8];
#pragma unroll
    for (int r = 0; r < 8; r++) acc[r] = 0.f;

    for (int f = 0; f < F; f += 4) {
        float w0 = sW[(f + 0) * Hd + col];
        float w1 = sW[(f + 1) * Hd + col];
        float w2 = sW[(f + 2) * Hd + col];
        float w3 = sW[(f + 3) * Hd + col];
#pragma unroll
        for (int r = 0; r < 8; r++) {
            float4 xv = __ldg((const float4*)(X + (size_t)(row0 + r * 4) * F + f));
            acc[r] += xv.x * w0 + xv.y * w1 + xv.z * w2 + xv.w * w3;
        }
    }
#pragma unroll
    for (int r = 0; r < 8; r++)
        Y[(size_t)(row0 + r * 4) * Hd + col] = acc[r];
}

// ---------------- O = act( acc/deg + X @ W + b ) ----------------
template <int F, bool RELU>
__global__ void __launch_bounds__(256)
combine_k(const float* __restrict__ A, const float* __restrict__ deg,
          const float* __restrict__ X, const float* __restrict__ W,
          const float* __restrict__ b, float* __restrict__ O, int N) {
    __shared__ float sW[F * Hd];
    __shared__ float sB[Hd];
    int tid = threadIdx.y * 64 + threadIdx.x;
    for (int i = tid; i < F * Hd; i += 256) sW[i] = W[i];
    if (tid < Hd) sB[tid] = b[tid];
    __syncthreads();

    int col  = threadIdx.x;
    int row0 = blockIdx.x * 32 + threadIdx.y;
    if (row0 >= N) return;

    float acc[8];
#pragma unroll
    for (int r = 0; r < 8; r++) acc[r] = 0.f;

    for (int f = 0; f < F; f += 4) {
        float w0 = sW[(f + 0) * Hd + col];
        float w1 = sW[(f + 1) * Hd + col];
        float w2 = sW[(f + 2) * Hd + col];
        float w3 = sW[(f + 3) * Hd + col];
#pragma unroll
        for (int r = 0; r < 8; r++) {
            float4 xv = __ldg((const float4*)(X + (size_t)(row0 + r * 4) * F + f));
            acc[r] += xv.x * w0 + xv.y * w1 + xv.z * w2 + xv.w * w3;
        }
    }
#pragma unroll
    for (int r = 0; r < 8; r++) {
        int row  = row0 + r * 4;
        float d  = __ldg(deg + row);
        float rd = 1.0f / fmaxf(d, 1.0f);
        float v  = acc[r] + sB[col] + __ldg(A + (size_t)row * Hd + col) * rd;
        O[(size_t)row * Hd + col] = RELU ? fmaxf(v, 0.f) : v;
    }
}

// ---------------- transpose W_dec1 [128,64] -> Wt [64,128] ----------------
__global__ void transpose_wdec(const float* __restrict__ W, float* __restrict__ Wt) {
    int t = blockIdx.x * 256 + threadIdx.x;
    if (t < 128 * 64) {
        int k = t >> 6, j = t & 63;
        Wt[j * 128 + k] = W[t];
    }
}

// ---------------- decoder: out[e] = W2 . relu([zc[row],zr[col]] @ Wd1 + b1) + b2 ----------------
__global__ void __launch_bounds__(256)
decoder_k(const float* __restrict__ zc, const float* __restrict__ zr,
          const int* __restrict__ eli, const float* __restrict__ Wt,
          const float* __restrict__ b1, const float* __restrict__ W2,
          const float* __restrict__ b2, float* __restrict__ out) {
    __shared__ float4 sW[Hd * 32];   // Wt as float4: [j][k4], 32KB
    __shared__ float  sB1[Hd];
    __shared__ float  sW2[Hd];
    const float4* Wt4 = (const float4*)Wt;
    for (int i = threadIdx.x; i < Hd * 32; i += 256) sW[i] = Wt4[i];
    if (threadIdx.x < Hd) { sB1[threadIdx.x] = b1[threadIdx.x]; sW2[threadIdx.x] = W2[threadIdx.x]; }
    __syncthreads();

    int e = blockIdx.x * 256 + threadIdx.x;
    if (e >= LN) return;
    int rw = __ldg(eli + e);
    int cl = __ldg(eli + LN + e);

    float4 za[16], zb[16];
    const float4* zcp = (const float4*)(zc + (size_t)rw * Hd);
    const float4* zrp = (const float4*)(zr + (size_t)cl * Hd);
#pragma unroll
    for (int i = 0; i < 16; i++) { za[i] = __ldg(zcp + i); zb[i] = __ldg(zrp + i); }

    float res = 0.f;
#pragma unroll 2
    for (int j = 0; j < Hd; j++) {
        float a = sB1[j];
#pragma unroll
        for (int k = 0; k < 16; k++) {
            float4 w = sW[j * 32 + k];
            a += za[k].x * w.x + za[k].y * w.y + za[k].z * w.z + za[k].w * w.w;
        }
#pragma unroll
        for (int k = 0; k < 16; k++) {
            float4 w = sW[j * 32 + 16 + k];
            a += zb[k].x * w.x + zb[k].y * w.y + zb[k].z * w.z + zb[k].w * w.w;
        }
        res += fmaxf(a, 0.f) * sW2[j];
    }
    out[e] = res + __ldg(b2);
}

// ---------------- host ----------------
extern "C" void kernel_launch(void* const* d_in, const int* in_sizes, int n_in,
                              void* d_out, int out_size) {
    const float* x_c   = (const float*)d_in[0];
    const float* x_r   = (const float*)d_in[1];
    const float* W1crl = (const float*)d_in[2];
    const float* W1crr = (const float*)d_in[3];
    const float* b1cr  = (const float*)d_in[4];
    const float* W1rcl = (const float*)d_in[5];
    const float* W1rcr = (const float*)d_in[6];
    const float* b1rc  = (const float*)d_in[7];
    const float* W2crl = (const float*)d_in[8];
    const float* W2crr = (const float*)d_in[9];
    const float* b2cr  = (const float*)d_in[10];
    const float* W2rcl = (const float*)d_in[11];
    const float* W2rcr = (const float*)d_in[12];
    const float* b2rc  = (const float*)d_in[13];
    const float* Wd1   = (const float*)d_in[14];
    const float* bd1   = (const float*)d_in[15];
    const float* Wd2   = (const float*)d_in[16];
    const float* bd2   = (const float*)d_in[17];
    const int*   e_cr  = (const int*)d_in[18];
    const int*   e_rc  = (const int*)d_in[19];
    const int*   eli   = (const int*)d_in[20];
    float*       out   = (float*)d_out;

    float *deg_c, *deg_r, *y, *acc, *hr, *hc, *zr, *zc, *wt;
    cudaGetSymbolAddress((void**)&deg_c, g_deg_c);
    cudaGetSymbolAddress((void**)&deg_r, g_deg_r);
    cudaGetSymbolAddress((void**)&y,   g_y);
    cudaGetSymbolAddress((void**)&acc, g_acc);
    cudaGetSymbolAddress((void**)&hr,  g_hr);
    cudaGetSymbolAddress((void**)&hc,  g_hc);
    cudaGetSymbolAddress((void**)&zr,  g_zr);
    cudaGetSymbolAddress((void**)&zc,  g_zc);
    cudaGetSymbolAddress((void**)&wt,  g_Wt);

    const dim3 gb(64, 4);
    const int NB   = (NN + 31) / 32;              // 3125
    const int EB   = (EN + 255) / 256;
    const int SB   = (EN * 16 + 255) / 256;       // 125000
    const size_t ACCB = (size_t)NN * Hd * sizeof(float);

    // degrees
    cudaMemsetAsync(deg_c, 0, NN * sizeof(float), 0);
    cudaMemsetAsync(deg_r, 0, NN * sizeof(float), 0);
    degree_k<<<EB, 256>>>(e_cr + EN, deg_r);
    degree_k<<<EB, 256>>>(e_rc + EN, deg_c);

    // ---- layer 1, c2r: h_r ----
    node_gemm<128><<<NB, gb>>>(x_c, W1crl, y, NN);
    cudaMemsetAsync(acc, 0, ACCB, 0);
    scatter_add_k<<<SB, 256>>>((const float4*)y, e_cr, e_cr + EN, acc);
    combine_k<64, true><<<NB, gb>>>(acc, deg_r, x_r, W1crr, b1cr, hr, NN);

    // ---- layer 1, r2c: h_c ----
    node_gemm<64><<<NB, gb>>>(x_r, W1rcl, y, NN);
    cudaMemsetAsync(acc, 0, ACCB, 0);
    scatter_add_k<<<SB, 256>>>((const float4*)y, e_rc, e_rc + EN, acc);
    combine_k<128, true><<<NB, gb>>>(acc, deg_c, x_c, W1rcr, b1rc, hc, NN);

    // ---- layer 2, c2r: z_r ----
    node_gemm<64><<<NB, gb>>>(hc, W2crl, y, NN);
    cudaMemsetAsync(acc, 0, ACCB, 0);
    scatter_add_k<<<SB, 256>>>((const float4*)y, e_cr, e_cr + EN, acc);
    combine_k<64, false><<<NB, gb>>>(acc, deg_r, hr, W2crr, b2cr, zr, NN);

    // ---- layer 2, r2c: z_c ----
    node_gemm<64><<<NB, gb>>>(hr, W2rcl, y, NN);
    cudaMemsetAsync(acc, 0, ACCB, 0);
    scatter_add_k<<<SB, 256>>>((const float4*)y, e_rc, e_rc + EN, acc);
    combine_k<64, false><<<NB, gb>>>(acc, deg_c, hc, W2rcr, b2rc, zc, NN);

    // ---- decoder ----
    transpose_wdec<<<32, 256>>>(Wd1, wt);
    decoder_k<<<(LN + 255) / 256, 256>>>(zc, zr, eli, wt, bd1, Wd2, bd2, out);
}

// round 4
// speedup vs baseline: 1.2284x; 1.2284x over previous
#include <cuda_runtime.h>
#include <cstdint>

#define NN   100000      // NC == NR
#define EN   2000000     // edges per direction
#define LN   500000      // label edges
#define Hd   64
#define NBLK 391         // ceil(NN/256)

// ---------------- scratch (device globals; no allocation) ----------------
__device__ __align__(16) float g_y  [NN * Hd];
__device__ __align__(16) float g_acc[NN * Hd];
__device__ __align__(16) float g_hr [NN * Hd];
__device__ __align__(16) float g_hc [NN * Hd];
__device__ __align__(16) float g_zr [NN * Hd];
__device__ __align__(16) float g_zc [NN * Hd];
__device__ __align__(16) float g_Wt [Hd * 128];
// CSR scratch
__device__ int g_cnt [NN];
__device__ int g_excl[NN];
__device__ int g_cur [NN];
__device__ int g_bsum[512];
__device__ int g_boff[512];
__device__ int g_ptr_r[NN + 1];
__device__ int g_ptr_c[NN + 1];
__device__ __align__(16) int g_cix_r[EN];
__device__ __align__(16) int g_cix_c[EN];

// ---------------- CSR build ----------------
__global__ void count_k(const int* __restrict__ dst, int* __restrict__ cnt) {
    int t = blockIdx.x * 256 + threadIdx.x;
    if (t < EN) atomicAdd(cnt + __ldg(dst + t), 1);
}

__global__ void scan_block_k(const int* __restrict__ cnt, int* __restrict__ excl,
                             int* __restrict__ bsum) {
    __shared__ int s[256];
    int tx = threadIdx.x;
    int i = blockIdx.x * 256 + tx;
    int v = (i < NN) ? cnt[i] : 0;
    s[tx] = v; __syncthreads();
    for (int off = 1; off < 256; off <<= 1) {
        int t = (tx >= off) ? s[tx - off] : 0;
        __syncthreads();
        s[tx] += t;
        __syncthreads();
    }
    if (i < NN) excl[i] = s[tx] - v;
    if (tx == 255) bsum[blockIdx.x] = s[255];
}

__global__ void scan_bsum_k(int* __restrict__ bsum, int* __restrict__ boff) {
    __shared__ int s[512];
    int tx = threadIdx.x;
    int v = (tx < NBLK) ? bsum[tx] : 0;
    s[tx] = v; __syncthreads();
    for (int off = 1; off < 512; off <<= 1) {
        int t = (tx >= off) ? s[tx - off] : 0;
        __syncthreads();
        s[tx] += t;
        __syncthreads();
    }
    if (tx < NBLK) boff[tx] = s[tx] - v;
}

__global__ void finalize_ptr_k(const int* __restrict__ excl, const int* __restrict__ boff,
                               int* __restrict__ ptr, int* __restrict__ cur) {
    int i = blockIdx.x * 256 + threadIdx.x;
    if (i < NN) {
        int p = excl[i] + boff[i >> 8];
        ptr[i] = p;
        cur[i] = p;
    }
    if (i == 0) ptr[NN] = EN;
}

__global__ void fill_k(const int* __restrict__ src, const int* __restrict__ dst,
                       int* __restrict__ cur, int* __restrict__ cix) {
    int t = blockIdx.x * 256 + threadIdx.x;
    if (t < EN) {
        int d = __ldg(dst + t);
        int pos = atomicAdd(cur + d, 1);
        cix[pos] = __ldg(src + t);
    }
}

// ---------------- gather mean: acc[row] = mean over neighbors of y[src] ----------------
// one warp per dst row; lane owns one float2 (pair) of the 64-wide feature
__global__ void __launch_bounds__(256)
gather_k(const float2* __restrict__ y2, const int* __restrict__ ptr,
         const int* __restrict__ cix, float2* __restrict__ acc) {
    int w = (blockIdx.x * 256 + threadIdx.x) >> 5;
    int lane = threadIdx.x & 31;
    if (w >= NN) return;
    int beg = __ldg(ptr + w), end = __ldg(ptr + w + 1);
    float ax0 = 0.f, ay0 = 0.f, ax1 = 0.f, ay1 = 0.f;
    int e = beg;
    for (; e + 4 <= end; e += 4) {
        int s0 = __ldg(cix + e + 0), s1 = __ldg(cix + e + 1);
        int s2 = __ldg(cix + e + 2), s3 = __ldg(cix + e + 3);
        float2 v0 = __ldg(y2 + (size_t)s0 * 32 + lane);
        float2 v1 = __ldg(y2 + (size_t)s1 * 32 + lane);
        float2 v2 = __ldg(y2 + (size_t)s2 * 32 + lane);
        float2 v3 = __ldg(y2 + (size_t)s3 * 32 + lane);
        ax0 += v0.x; ay0 += v0.y;
        ax1 += v1.x; ay1 += v1.y;
        ax0 += v2.x; ay0 += v2.y;
        ax1 += v3.x; ay1 += v3.y;
    }
    for (; e < end; e++) {
        int s = __ldg(cix + e);
        float2 v = __ldg(y2 + (size_t)s * 32 + lane);
        ax0 += v.x; ay0 += v.y;
    }
    float inv = 1.0f / fmaxf((float)(end - beg), 1.0f);
    float2 r;
    r.x = (ax0 + ax1) * inv;
    r.y = (ay0 + ay1) * inv;
    acc[(size_t)w * 32 + lane] = r;
}

// ---------------- Y[N,64] = X[N,F] @ W[F,64] ----------------
// blockDim (64,4); 32 rows per block; 8 rows per thread
template <int F>
__global__ void __launch_bounds__(256)
node_gemm(const float* __restrict__ X, const float* __restrict__ W,
          float* __restrict__ Y, int N) {
    __shared__ float sW[F * Hd];
    int tid = threadIdx.y * 64 + threadIdx.x;
    for (int i = tid; i < F * Hd; i += 256) sW[i] = W[i];
    __syncthreads();

    int col  = threadIdx.x;
    int row0 = blockIdx.x * 32 + threadIdx.y;
    if (row0 >= N) return;

    float acc[8];
#pragma unroll
    for (int r = 0; r < 8; r++) acc[r] = 0.f;

    for (int f = 0; f < F; f += 4) {
        float w0 = sW[(f + 0) * Hd + col];
        float w1 = sW[(f + 1) * Hd + col];
        float w2 = sW[(f + 2) * Hd + col];
        float w3 = sW[(f + 3) * Hd + col];
#pragma unroll
        for (int r = 0; r < 8; r++) {
            float4 xv = __ldg((const float4*)(X + (size_t)(row0 + r * 4) * F + f));
            acc[r] += xv.x * w0 + xv.y * w1 + xv.z * w2 + xv.w * w3;
        }
    }
#pragma unroll
    for (int r = 0; r < 8; r++)
        Y[(size_t)(row0 + r * 4) * Hd + col] = acc[r];
}

// ---------------- O = act( A + X @ W + b )  (A already mean-divided) ----------------
template <int F, bool RELU>
__global__ void __launch_bounds__(256)
combine_k(const float* __restrict__ A,
          const float* __restrict__ X, const float* __restrict__ W,
          const float* __restrict__ b, float* __restrict__ O, int N) {
    __shared__ float sW[F * Hd];
    __shared__ float sB[Hd];
    int tid = threadIdx.y * 64 + threadIdx.x;
    for (int i = tid; i < F * Hd; i += 256) sW[i] = W[i];
    if (tid < Hd) sB[tid] = b[tid];
    __syncthreads();

    int col  = threadIdx.x;
    int row0 = blockIdx.x * 32 + threadIdx.y;
    if (row0 >= N) return;

    float acc[8];
#pragma unroll
    for (int r = 0; r < 8; r++) acc[r] = 0.f;

    for (int f = 0; f < F; f += 4) {
        float w0 = sW[(f + 0) * Hd + col];
        float w1 = sW[(f + 1) * Hd + col];
        float w2 = sW[(f + 2) * Hd + col];
        float w3 = sW[(f + 3) * Hd + col];
#pragma unroll
        for (int r = 0; r < 8; r++) {
            float4 xv = __ldg((const float4*)(X + (size_t)(row0 + r * 4) * F + f));
            acc[r] += xv.x * w0 + xv.y * w1 + xv.z * w2 + xv.w * w3;
        }
    }
#pragma unroll
    for (int r = 0; r < 8; r++) {
        int row = row0 + r * 4;
        float v = acc[r] + sB[col] + __ldg(A + (size_t)row * Hd + col);
        O[(size_t)row * Hd + col] = RELU ? fmaxf(v, 0.f) : v;
    }
}

// ---------------- transpose W_dec1 [128,64] -> Wt [64,128] ----------------
__global__ void transpose_wdec(const float* __restrict__ W, float* __restrict__ Wt) {
    int t = blockIdx.x * 256 + threadIdx.x;
    if (t < 128 * 64) {
        int k = t >> 6, j = t & 63;
        Wt[j * 128 + k] = W[t];
    }
}

// ---------------- decoder: out[e] = W2 . relu([zc[row],zr[col]] @ Wd1 + b1) + b2 ----------------
__global__ void __launch_bounds__(256)
decoder_k(const float* __restrict__ zc, const float* __restrict__ zr,
          const int* __restrict__ eli, const float* __restrict__ Wt,
          const float* __restrict__ b1, const float* __restrict__ W2,
          const float* __restrict__ b2, float* __restrict__ out) {
    __shared__ __align__(16) float4 sW[Hd * 32];   // Wt as float4: [j][k4], 32KB
    __shared__ float  sB1[Hd];
    __shared__ float  sW2[Hd];
    const float4* Wt4 = (const float4*)Wt;
    for (int i = threadIdx.x; i < Hd * 32; i += 256) sW[i] = Wt4[i];
    if (threadIdx.x < Hd) { sB1[threadIdx.x] = b1[threadIdx.x]; sW2[threadIdx.x] = W2[threadIdx.x]; }
    __syncthreads();

    int e = blockIdx.x * 256 + threadIdx.x;
    if (e >= LN) return;
    int rw = __ldg(eli + e);
    int cl = __ldg(eli + LN + e);

    float4 za[16], zb[16];
    const float4* zcp = (const float4*)(zc + (size_t)rw * Hd);
    const float4* zrp = (const float4*)(zr + (size_t)cl * Hd);
#pragma unroll
    for (int i = 0; i < 16; i++) { za[i] = __ldg(zcp + i); zb[i] = __ldg(zrp + i); }

    float res = 0.f;
#pragma unroll 2
    for (int j = 0; j < Hd; j++) {
        float a = sB1[j];
#pragma unroll
        for (int k = 0; k < 16; k++) {
            float4 w = sW[j * 32 + k];
            a += za[k].x * w.x + za[k].y * w.y + za[k].z * w.z + za[k].w * w.w;
        }
#pragma unroll
        for (int k = 0; k < 16; k++) {
            float4 w = sW[j * 32 + 16 + k];
            a += zb[k].x * w.x + zb[k].y * w.y + zb[k].z * w.z + zb[k].w * w.w;
        }
        res += fmaxf(a, 0.f) * sW2[j];
    }
    out[e] = res + __ldg(b2);
}

// ---------------- host ----------------
extern "C" void kernel_launch(void* const* d_in, const int* in_sizes, int n_in,
                              void* d_out, int out_size) {
    const float* x_c   = (const float*)d_in[0];
    const float* x_r   = (const float*)d_in[1];
    const float* W1crl = (const float*)d_in[2];
    const float* W1crr = (const float*)d_in[3];
    const float* b1cr  = (const float*)d_in[4];
    const float* W1rcl = (const float*)d_in[5];
    const float* W1rcr = (const float*)d_in[6];
    const float* b1rc  = (const float*)d_in[7];
    const float* W2crl = (const float*)d_in[8];
    const float* W2crr = (const float*)d_in[9];
    const float* b2cr  = (const float*)d_in[10];
    const float* W2rcl = (const float*)d_in[11];
    const float* W2rcr = (const float*)d_in[12];
    const float* b2rc  = (const float*)d_in[13];
    const float* Wd1   = (const float*)d_in[14];
    const float* bd1   = (const float*)d_in[15];
    const float* Wd2   = (const float*)d_in[16];
    const float* bd2   = (const float*)d_in[17];
    const int*   e_cr  = (const int*)d_in[18];
    const int*   e_rc  = (const int*)d_in[19];
    const int*   eli   = (const int*)d_in[20];
    float*       out   = (float*)d_out;

    float *y, *acc, *hr, *hc, *zr, *zc, *wt;
    int *cnt, *excl, *cur, *bsum, *boff, *ptr_r, *ptr_c, *cix_r, *cix_c;
    cudaGetSymbolAddress((void**)&y,    g_y);
    cudaGetSymbolAddress((void**)&acc,  g_acc);
    cudaGetSymbolAddress((void**)&hr,   g_hr);
    cudaGetSymbolAddress((void**)&hc,   g_hc);
    cudaGetSymbolAddress((void**)&zr,   g_zr);
    cudaGetSymbolAddress((void**)&zc,   g_zc);
    cudaGetSymbolAddress((void**)&wt,   g_Wt);
    cudaGetSymbolAddress((void**)&cnt,  g_cnt);
    cudaGetSymbolAddress((void**)&excl, g_excl);
    cudaGetSymbolAddress((void**)&cur,  g_cur);
    cudaGetSymbolAddress((void**)&bsum, g_bsum);
    cudaGetSymbolAddress((void**)&boff, g_boff);
    cudaGetSymbolAddress((void**)&ptr_r, g_ptr_r);
    cudaGetSymbolAddress((void**)&ptr_c, g_ptr_c);
    cudaGetSymbolAddress((void**)&cix_r, g_cix_r);
    cudaGetSymbolAddress((void**)&cix_c, g_cix_c);

    const int EB = (EN + 255) / 256;
    const int CB = (NN + 255) / 256;       // 391
    const int NB = (NN + 31) / 32;         // 3125
    const int GB = (NN * 32 + 255) / 256;  // 12500
    const dim3 gb(64, 4);

    // ---- build CSR for c2r (dst = recipe) ----
    cudaMemsetAsync(cnt, 0, NN * sizeof(int), 0);
    count_k<<<EB, 256>>>(e_cr + EN, cnt);
    scan_block_k<<<CB, 256>>>(cnt, excl, bsum);
    scan_bsum_k<<<1, 512>>>(bsum, boff);
    finalize_ptr_k<<<CB, 256>>>(excl, boff, ptr_r, cur);
    fill_k<<<EB, 256>>>(e_cr, e_cr + EN, cur, cix_r);

    // ---- build CSR for r2c (dst = customer) ----
    cudaMemsetAsync(cnt, 0, NN * sizeof(int), 0);
    count_k<<<EB, 256>>>(e_rc + EN, cnt);
    scan_block_k<<<CB, 256>>>(cnt, excl, bsum);
    scan_bsum_k<<<1, 512>>>(bsum, boff);
    finalize_ptr_k<<<CB, 256>>>(excl, boff, ptr_c, cur);
    fill_k<<<EB, 256>>>(e_rc, e_rc + EN, cur, cix_c);

    // ---- layer 1, c2r: h_r ----
    node_gemm<128><<<NB, gb>>>(x_c, W1crl, y, NN);
    gather_k<<<GB, 256>>>((const float2*)y, ptr_r, cix_r, (float2*)acc);
    combine_k<64, true><<<NB, gb>>>(acc, x_r, W1crr, b1cr, hr, NN);

    // ---- layer 1, r2c: h_c ----
    node_gemm<64><<<NB, gb>>>(x_r, W1rcl, y, NN);
    gather_k<<<GB, 256>>>((const float2*)y, ptr_c, cix_c, (float2*)acc);
    combine_k<128, true><<<NB, gb>>>(acc, x_c, W1rcr, b1rc, hc, NN);

    // ---- layer 2, c2r: z_r ----
    node_gemm<64><<<NB, gb>>>(hc, W2crl, y, NN);
    gather_k<<<GB, 256>>>((const float2*)y, ptr_r, cix_r, (float2*)acc);
    combine_k<64, false><<<NB, gb>>>(acc, hr, W2crr, b2cr, zr, NN);

    // ---- layer 2, r2c: z_c ----
    node_gemm<64><<<NB, gb>>>(hr, W2rcl, y, NN);
    gather_k<<<GB, 256>>>((const float2*)y, ptr_c, cix_c, (float2*)acc);
    combine_k<64, false><<<NB, gb>>>(acc, hc, W2rcr, b2rc, zc, NN);

    // ---- decoder ----
    transpose_wdec<<<32, 256>>>(Wd1, wt);
    decoder_k<<<(LN + 255) / 256, 256>>>(zc, zr, eli, wt, bd1, Wd2, bd2, out);
}